// round 10
// baseline (speedup 1.0000x reference)
#include <cuda_runtime.h>
#include <cuda_bf16.h>

// Cascaded 16-tap FIR pair == single 33-tap causal conv for columns i >= 32:
//   y[i] = x[i] + sum_{j=1}^{32} g[j] * x[i-j],  g = [1,h] (*) [1,h_rev]
// Columns [0,32) computed exactly (v-mask aware) by threads 0-3 on row-start tiles.
//
// Persistent CTAs (592 = 4/SM) + double-buffered cp.async prefetch.
// RPT=8 so the full live set (40-float window + 8 acc + 8 taps ~ 60 regs)
// fits under the 64-reg/4-CTA cap -> no window rematerialization, the
// 256-FFMA burst per thread runs uninterrupted. smem tile padded 8->12
// floats per segment: conflict-free LDS.128 at the 8-float thread stride.
//
// B=256 rows, N=131072 cols, F=16.

#define F       16
#define GT      33
#define THREADS 256
#define RPT     8
#define TILE    (THREADS * RPT)    // 2048
#define HALO    32
#define NCOL    131072
#define NROW    256
#define TPR     (NCOL / TILE)      // 64 tiles per row
#define NTILES  (TPR * NROW)       // 16384
#define NBLK    592                // 4 per SM

#define SEGP    12                         // 8-float segment padded to 12
#define NSEG    ((TILE + HALO) / 8)        // 260 segments
#define BUFSZ   (NSEG * SEGP)              // 3120 floats = 12480 B
#define NVEC    ((TILE + HALO) / 4)        // 520 float4 per tile

__device__ __forceinline__ void cp16(unsigned dst, const float4* src, int sz) {
    asm volatile("cp.async.cg.shared.global [%0], [%1], 16, %2;"
                 :: "r"(dst), "l"(src), "r"(sz));
}
__device__ __forceinline__ void cp_commit() {
    asm volatile("cp.async.commit_group;");
}
template <int N> __device__ __forceinline__ void cp_wait() {
    asm volatile("cp.async.wait_group %0;" :: "n"(N));
}

// float4 vk -> padded smem float index (vk>>1)*12 + (vk&1)*4
__device__ __forceinline__ void stage_tile(unsigned sb, const float* x,
                                           int t, int tid)
{
    const int row = t / TPR;
    const int tir = t % TPR;
    const float4* src = reinterpret_cast<const float4*>(
        x + (size_t)row * NCOL + tir * TILE - HALO);
    const bool z = (tir == 0);
#pragma unroll
    for (int vk = tid; vk < NVEC; vk += THREADS) {
        const int sz = (z && vk < HALO / 4) ? 0 : 16;
        const float4* sp = sz ? (src + vk) : reinterpret_cast<const float4*>(x);
        cp16(sb + ((((vk >> 1) * SEGP) + (vk & 1) * 4) << 2), sp, sz);
    }
}

__global__ __launch_bounds__(THREADS, 4)
void fir2_fused(const float* __restrict__ x,
                const float* __restrict__ h,
                float* __restrict__ y)
{
    __shared__ float  sg[GT + 3];
    __shared__ float4 sgc[8];              // taps g[1..32] repacked, 16B aligned
    __shared__ float  sx[2][BUFSZ];        // double-buffered padded tiles

    const int tid = threadIdx.x;

    // ---- per-block combined taps (threads 0..32) ----------------------------
    if (tid < GT) {
        const int j = tid;
        float acc = 0.0f;
        const int a0 = (j > F) ? (j - F) : 0;
        const int a1 = (j < F) ? j : F;
        for (int a = a0; a <= a1; a++) {
            const float ka = (a == 0) ? 1.0f : __ldg(h + a - 1);
            const int bb = j - a;
            const float kb = (bb == 0) ? 1.0f : __ldg(h + F - bb);
            acc += ka * kb;
        }
        sg[j] = acc;
    }

    unsigned sbase[2];
    sbase[0] = (unsigned)__cvta_generic_to_shared(&sx[0][0]);
    sbase[1] = (unsigned)__cvta_generic_to_shared(&sx[1][0]);

    // ---- prefetch first tile ------------------------------------------------
    int t = blockIdx.x;
    stage_tile(sbase[0], x, t, tid);
    cp_commit();
    __syncthreads();                       // sg ready

    // repack taps: ((float*)sgc)[k] = g[k+1], k in [0,32)
    if (tid < 32) reinterpret_cast<float*>(sgc)[tid] = sg[tid + 1];
    // visible to all threads via the in-loop __syncthreads before compute

    int buf = 0;
    for (; t < NTILES; t += NBLK, buf ^= 1) {
        const int tn = t + NBLK;
        if (tn < NTILES) stage_tile(sbase[buf ^ 1], x, tn, tid);
        cp_commit();
        cp_wait<1>();                      // current tile's group complete
        __syncthreads();

        const int row = t / TPR;
        const int tir = t % TPR;
        const int t0  = tir * TILE;
        const size_t rowoff = (size_t)row * NCOL;
        const float* sxc = sx[buf];

        if (!(tir == 0 && tid < 4)) {
            // window: w[c] = x[row][t0 + tid*8 - 32 + c], c in [0,40)
            float w[RPT + HALO];
            {
                const int k0 = tid * RPT;
#pragma unroll
                for (int q = 0; q < 10; q++) {
                    const int k = k0 + 4 * q;
                    *reinterpret_cast<float4*>(&w[4 * q]) =
                        *reinterpret_cast<const float4*>(
                            &sxc[(k >> 3) * SEGP + (k & 7)]);
                }
            }

            float acc[RPT];
#pragma unroll
            for (int r = 0; r < RPT; r++) acc[r] = w[r + 32];   // identity tap

#pragma unroll
            for (int c = 0; c < 4; c++) {
                float tp[8];
                *reinterpret_cast<float4*>(&tp[0]) = sgc[2 * c];
                *reinterpret_cast<float4*>(&tp[4]) = sgc[2 * c + 1];
#pragma unroll
                for (int r = 0; r < RPT; r++) {
#pragma unroll
                    for (int k = 0; k < 8; k++)
                        acc[r] = fmaf(tp[k], w[r + 31 - 8 * c - k], acc[r]);
                }
            }

            float4* yo = reinterpret_cast<float4*>(y + rowoff + t0 + tid * RPT);
            yo[0] = make_float4(acc[0], acc[1], acc[2], acc[3]);
            yo[1] = make_float4(acc[4], acc[5], acc[6], acc[7]);
        } else {
            // ---- exact masked two-stage result for columns [0,32) ----------
            if (tid < 2) {
                float4* yo = reinterpret_cast<float4*>(y + rowoff + tid * RPT);
                yo[0] = make_float4(0.f, 0.f, 0.f, 0.f);   // y[0..16) = 0
                yo[1] = make_float4(0.f, 0.f, 0.f, 0.f);
            } else {
                const float* xr = x + rowoff;
                float xa[32];
#pragma unroll
                for (int c = 0; c < 32; c++) xa[c] = xr[c];
                float hh[F];
#pragma unroll
                for (int j = 0; j < F; j++) hh[j] = __ldg(h + j);

                float va[F];           // v[16..31]
#pragma unroll
                for (int tt = 0; tt < F; tt++) {
                    const int k = F + tt;
                    float a2 = xa[k];
#pragma unroll
                    for (int j = 0; j < F; j++)
                        a2 = fmaf(hh[j], xa[k - 1 - j], a2);
                    va[tt] = a2;
                }
                // this thread's outputs: i in [16 + 8*(tid-2), 24 + 8*(tid-2))
                const int ib = F + RPT * (tid - 2);
                float ya[RPT];
#pragma unroll
                for (int tt = 0; tt < RPT; tt++) {
                    const int i = ib + tt;
                    float a2 = va[i - F];
#pragma unroll
                    for (int m = 0; m < F; m++) {
                        const int k = i - F + m;   // v index; masked if < 16
                        if (k >= F) a2 = fmaf(hh[m], va[k - F], a2);
                    }
                    ya[tt] = a2;
                }
                float4* yo = reinterpret_cast<float4*>(y + rowoff + ib);
                yo[0] = make_float4(ya[0], ya[1], ya[2], ya[3]);
                yo[1] = make_float4(ya[4], ya[5], ya[6], ya[7]);
            }
        }
        __syncthreads();               // protect sx[buf^1] (being prefetched)
                                       // and sgc on the first iteration
    }
}

extern "C" void kernel_launch(void* const* d_in, const int* in_sizes, int n_in,
                              void* d_out, int out_size)
{
    const float* x = (const float*)d_in[0];   // (256, 131072) f32
    const float* h = (const float*)d_in[1];   // (1, 16) f32
    float* y = (float*)d_out;                 // (256, 131072) f32

    fir2_fused<<<NBLK, THREADS>>>(x, h, y);
}